// round 9
// baseline (speedup 1.0000x reference)
#include <cuda_runtime.h>
#include <cstdint>

#define SEQ 32
#define EDIM 256
#define HDIM 256
#define GDIM 1024
#define NTHREADS 256

#define XSP 260                       // padded x-tile row stride (floats), kernel A
#define HS  264                       // h row stride (floats): mod32=8 -> conflict-free LDS.64

// ---------------- device scratch ----------------
// W_ih fragments: [g8][kb32][nf16][lane32] uint2
__device__ __align__(16) uint2 g_wih_pk[8*32*16*32];
// W_hh fragments paired: [g8][kb32][j8][lane32] uint4 (j pairs nf 2j,2j+1)
__device__ __align__(16) uint4 g_whh_pk4[8*32*8*32];
__device__ float g_bperm[GDIM];
// xg fragment-native: block[(tile*32+s)*8+g] of 4096 floats = [nfg32][lane32] float4
__device__ __align__(16) float g_xg[(size_t)128*32*8*4096];

__device__ __forceinline__ float tf32_round_f(float x) {
    float r; asm("cvt.rna.tf32.f32 %0, %1;" : "=f"(r) : "f"(x)); return r;
}
__device__ __forceinline__ uint32_t tf32_round_u(float x) {
    uint32_t r; asm("cvt.rna.tf32.f32 %0, %1;" : "=r"(r) : "f"(x)); return r;
}

#define MMA_TF32(d, a, b0, b1)                                              \
    asm volatile("mma.sync.aligned.m16n8k8.row.col.f32.tf32.tf32.f32 "      \
                 "{%0,%1,%2,%3}, {%4,%5,%6,%7}, {%8,%9}, {%0,%1,%2,%3};"    \
                 : "+f"((d)[0]), "+f"((d)[1]), "+f"((d)[2]), "+f"((d)[3])   \
                 : "r"((a)[0]), "r"((a)[1]), "r"((a)[2]), "r"((a)[3]),      \
                   "r"(b0), "r"(b1))

__device__ __forceinline__ float sigmoidf_(float x) {
    return 1.0f / (1.0f + __expf(-x));
}

// =================== prep: permute + tf32 + fragment-pack ===================
__global__ void prep_kernel(const float* __restrict__ wih,
                            const float* __restrict__ whh,
                            const float* __restrict__ bih,
                            const float* __restrict__ bhh) {
    int i = blockIdx.x * blockDim.x + threadIdx.x;   // 0..131071
    // W_ih uint2 fragments
    if (i < 8*32*16*32) {
        int lane = i & 31, nf = (i >> 5) & 15, kb = (i >> 9) & 31, g = (i >> 14) & 7;
        int grp = lane >> 2, tg = lane & 3;
        int colperm = g*128 + nf*8 + grp;
        int unit = colperm >> 2, gate = colperm & 3;
        int orow = gate*256 + unit, kk = kb*8 + tg;
        uint2 v;
        v.x = tf32_round_u(wih[orow*256 + kk]);
        v.y = tf32_round_u(wih[orow*256 + kk + 4]);
        g_wih_pk[i] = v;
    }
    // W_hh uint4 paired fragments
    if (i < 8*32*8*32) {
        int lane = i & 31, j = (i >> 5) & 7, kb = (i >> 8) & 31, g = (i >> 13) & 7;
        int grp = lane >> 2, tg = lane & 3;
        uint4 v;
        #pragma unroll
        for (int h = 0; h < 2; ++h) {
            int nf = 2*j + h;
            int colperm = g*128 + nf*8 + grp;
            int unit = colperm >> 2, gate = colperm & 3;
            int orow = gate*256 + unit, kk = kb*8 + tg;
            uint32_t b0 = tf32_round_u(whh[orow*256 + kk]);
            uint32_t b1 = tf32_round_u(whh[orow*256 + kk + 4]);
            if (h == 0) { v.x = b0; v.y = b1; } else { v.z = b0; v.w = b1; }
        }
        g_whh_pk4[i] = v;
    }
    if (i < GDIM) {
        int u2 = i >> 2, g2 = i & 3;
        g_bperm[i] = bih[g2*256 + u2] + bhh[g2*256 + u2];
    }
}

// =================== kernel A: xg = x @ W_ih^T + b (weight-stationary) ===================
#define A_WS_BYTES 131072
#define A_XS_OFF   (A_WS_BYTES/4)
#define SMEM_A_BYTES (A_WS_BYTES + 2*32*XSP*4)

__global__ __launch_bounds__(NTHREADS, 1)
void xg_gemm_kernel(const float* __restrict__ x) {
    extern __shared__ float sm[];
    uint2* Ws = (uint2*)sm;                 // [kb32][nf16][lane32]
    float* Xs = sm + A_XS_OFF;              // [2 steps][32 rows][XSP]

    const int tid  = threadIdx.x;
    const int lane = tid & 31;
    const int w    = tid >> 5;
    const int grp  = lane >> 2;
    const int tg   = lane & 3;
    const int g    = blockIdx.x & 7;
    const int rg   = blockIdx.x >> 3;
    const int t    = w >> 2;        // step within staged pair
    const int cg   = w & 3;         // col group (32 cols)

    {
        const uint4* src = (const uint4*)(g_wih_pk + (size_t)g*16384);
        uint4* dst = (uint4*)Ws;
        #pragma unroll
        for (int j = tid; j < 8192; j += NTHREADS) dst[j] = src[j];
    }

    float4 rbuf[16];
    {
        int rt = rg*8, s0 = 0;
        #pragma unroll
        for (int j = 0; j < 16; ++j) {
            int t2 = j >> 3, jj = j & 7;
            int fi = tid + jj*256, r = fi >> 6, cq = fi & 63;
            rbuf[j] = *(const float4*)(x + (((size_t)(rt*32 + r))*32 + (s0 + t2))*256 + cq*4);
        }
    }

    for (int it = 0; it < 128; ++it) {
        const int rt = rg*8 + (it >> 4);
        const int s0 = (it & 15)*2;

        __syncthreads();
        #pragma unroll
        for (int j = 0; j < 16; ++j) {
            int t2 = j >> 3, jj = j & 7;
            int fi = tid + jj*256, r = fi >> 6, cq = fi & 63;
            float* dp = &Xs[(t2*32 + r)*XSP + cq*4];
            dp[0] = tf32_round_f(rbuf[j].x);
            dp[1] = tf32_round_f(rbuf[j].y);
            dp[2] = tf32_round_f(rbuf[j].z);
            dp[3] = tf32_round_f(rbuf[j].w);
        }
        __syncthreads();

        if (it + 1 < 128) {
            int rt2 = rg*8 + ((it + 1) >> 4);
            int s02 = ((it + 1) & 15)*2;
            #pragma unroll
            for (int j = 0; j < 16; ++j) {
                int t2 = j >> 3, jj = j & 7;
                int fi = tid + jj*256, r = fi >> 6, cq = fi & 63;
                rbuf[j] = *(const float4*)(x + (((size_t)(rt2*32 + r))*32 + (s02 + t2))*256 + cq*4);
            }
        }

        float d[2][4][4];
        #pragma unroll
        for (int nf = 0; nf < 4; ++nf) {
            int col = g*128 + (cg*4 + nf)*8 + 2*tg;
            float b0 = g_bperm[col], b1 = g_bperm[col + 1];
            d[0][nf][0] = b0; d[0][nf][1] = b1; d[0][nf][2] = b0; d[0][nf][3] = b1;
            d[1][nf][0] = b0; d[1][nf][1] = b1; d[1][nf][2] = b0; d[1][nf][3] = b1;
        }
        const uint32_t* A = (const uint32_t*)(Xs + t*32*XSP);
        #pragma unroll 4
        for (int kb = 0; kb < 32; ++kb) {
            const int k8 = kb*8;
            uint32_t a[2][4];
            #pragma unroll
            for (int mh = 0; mh < 2; ++mh) {
                int r0 = mh*16 + grp;
                a[mh][0] = A[r0*XSP + k8 + tg];
                a[mh][1] = A[(r0+8)*XSP + k8 + tg];
                a[mh][2] = A[r0*XSP + k8 + 4 + tg];
                a[mh][3] = A[(r0+8)*XSP + k8 + 4 + tg];
            }
            #pragma unroll
            for (int nf = 0; nf < 4; ++nf) {
                uint2 b = Ws[(kb*16 + cg*4 + nf)*32 + lane];
                MMA_TF32(d[0][nf], a[0], b.x, b.y);
                MMA_TF32(d[1][nf], a[1], b.x, b.y);
            }
        }
        // store fragments: one float4 per (nfg, lane) — coalesced 512B per store
        {
            float4* xp = (float4*)(g_xg + (((size_t)(rt*32 + s0 + t)*8 + g)*4096));
            #pragma unroll
            for (int mh = 0; mh < 2; ++mh)
                #pragma unroll
                for (int nf = 0; nf < 4; ++nf) {
                    int nfg = mh*16 + cg*4 + nf;
                    xp[nfg*32 + lane] = make_float4(d[mh][nf][0], d[mh][nf][1],
                                                    d[mh][nf][2], d[mh][nf][3]);
                }
        }
    }
}

// =================== kernel B: recurrence (per-CTA local, W_hh only) ===================
#define SMEM_B_BYTES (2*32*HS*4)   // 67,584 B

__global__ __launch_bounds__(NTHREADS, 1)
void lstm_rec_kernel(float* __restrict__ out) {
    extern __shared__ float sm[];
    float* Hb = sm;   // two ping-pong h buffers [32][HS], k-paired layout

    const int tid  = threadIdx.x;
    const int lane = tid & 31;
    const int w    = tid >> 5;              // 0..7, owns gate cols w*128..+127
    const int grp  = lane >> 2;
    const int tg   = lane & 3;
    const int tgl  = tg & 1;
    const int tgh  = tg >> 1;
    const int tile = blockIdx.x;            // row tile 0..127
    const long rowbase = (long)tile * 32;

    float cst[2][16];
    #pragma unroll
    for (int a = 0; a < 2; ++a)
        #pragma unroll
        for (int b = 0; b < 16; ++b) cst[a][b] = 0.0f;

    for (int s = 0; s < SEQ; ++s) {
        const float* Hcur = Hb + (s & 1) * 32*HS;
        float*       Hnxt = Hb + ((s + 1) & 1) * 32*HS;

        // init accumulators from xg: 32x LDG.128, fully coalesced
        float d[2][16][4];
        {
            const float4* xp = (const float4*)(g_xg + (((size_t)(tile*32 + s)*8 + w)*4096));
            #pragma unroll
            for (int mh = 0; mh < 2; ++mh)
                #pragma unroll
                for (int nf = 0; nf < 16; ++nf) {
                    float4 v = xp[(mh*16 + nf)*32 + lane];
                    d[mh][nf][0] = v.x; d[mh][nf][1] = v.y;
                    d[mh][nf][2] = v.z; d[mh][nf][3] = v.w;
                }
        }

        if (s > 0) {
            #pragma unroll 2
            for (int kb = 0; kb < 32; ++kb) {
                const int k8 = kb*8;
                // k-paired LDS.64 loads: {k8+tg, k8+4+tg} adjacent
                uint32_t a[2][4];
                #pragma unroll
                for (int mh = 0; mh < 2; ++mh) {
                    int r0 = mh*16 + grp;
                    float2 v0 = *(const float2*)(Hcur + r0*HS + k8 + tg*2);
                    float2 v1 = *(const float2*)(Hcur + (r0+8)*HS + k8 + tg*2);
                    a[mh][0] = __float_as_uint(v0.x);
                    a[mh][2] = __float_as_uint(v0.y);
                    a[mh][1] = __float_as_uint(v1.x);
                    a[mh][3] = __float_as_uint(v1.y);
                }
                const uint4* bp = g_whh_pk4 + ((size_t)(w*32 + kb)*8)*32 + lane;
                #pragma unroll
                for (int j = 0; j < 8; ++j) {
                    uint4 b = bp[j*32];
                    MMA_TF32(d[0][2*j],   a[0], b.x, b.y);
                    MMA_TF32(d[1][2*j],   a[1], b.x, b.y);
                    MMA_TF32(d[0][2*j+1], a[0], b.z, b.w);
                    MMA_TF32(d[1][2*j+1], a[1], b.z, b.w);
                }
            }
        }

        // activation in registers
        #pragma unroll
        for (int mh = 0; mh < 2; ++mh) {
            #pragma unroll
            for (int nf = 0; nf < 16; ++nf) {
                float c0 = d[mh][nf][0], c1 = d[mh][nf][1];
                float c2 = d[mh][nf][2], c3 = d[mh][nf][3];
                float x0 = __shfl_xor_sync(0xffffffffu, tgl ? c0 : c2, 1);
                float x1 = __shfl_xor_sync(0xffffffffu, tgl ? c1 : c3, 1);
                float gi = tgl ? x0 : c0;
                float gf = tgl ? x1 : c1;
                float gg = tgl ? c2 : x0;
                float go = tgl ? c3 : x1;
                int row = grp + 8*tgl + 16*mh;
                int u   = w*32 + 2*nf + tgh;          // global unit 0..255
                float cv = sigmoidf_(gf) * cst[mh][nf]
                         + sigmoidf_(gi) * tanhf(gg);
                cst[mh][nf] = cv;
                float h = sigmoidf_(go) * tanhf(cv);
                // k-paired store position: u = kb*8 + r -> q = kb*8 + 2*(r&3) + (r>>2)
                int q = (u & ~7) + 2*(u & 3) + ((u >> 2) & 1);
                Hnxt[row*HS + q] = tf32_round_f(h);
                if (s == SEQ - 1) out[(rowbase + row)*HDIM + u] = h;
            }
        }
        __syncthreads();
    }
}

extern "C" void kernel_launch(void* const* d_in, const int* in_sizes, int n_in,
                              void* d_out, int out_size) {
    const float* x   = (const float*)d_in[0];
    const float* wih = (const float*)d_in[1];
    const float* whh = (const float*)d_in[2];
    const float* bih = (const float*)d_in[3];
    const float* bhh = (const float*)d_in[4];
    float* out = (float*)d_out;

    cudaFuncSetAttribute(xg_gemm_kernel,
                         cudaFuncAttributeMaxDynamicSharedMemorySize, SMEM_A_BYTES);
    cudaFuncSetAttribute(lstm_rec_kernel,
                         cudaFuncAttributeMaxDynamicSharedMemorySize, SMEM_B_BYTES);

    prep_kernel<<<512, 256>>>(wih, whh, bih, bhh);
    xg_gemm_kernel<<<128, NTHREADS, SMEM_A_BYTES>>>(x);
    lstm_rec_kernel<<<128, NTHREADS, SMEM_B_BYTES>>>(out);
}

// round 10
// speedup vs baseline: 1.9361x; 1.9361x over previous
#include <cuda_runtime.h>
#include <cuda_fp16.h>
#include <cstdint>

#define SEQ 32
#define EDIM 256
#define HDIM 256
#define GDIM 1024
#define ROWS 32
#define NCTAS 128
#define NTHREADS 256

#define XSW 132   // half2 words per row (264 halves): conflict-free for (8*grp+tg) patterns
#define SMEM_FLOATS 0
#define XS_WORDS (ROWS*XSW)             // one tile, half2 words
#define SMEM_BYTES ((XS_WORDS + 2*XS_WORDS)*4)   // Xs + 2 H buffers = 50,688 B

// fp16 B-fragment packed weights, uint4 pairs (nf 2j, 2j+1):
// index = ((w*32 + kc)*8 + j)*32 + lane ; kc 0..15 = X part (W_ih), 16..31 = H part (W_hh)
__device__ __align__(16) uint4 g_wpk4[8*32*8*32];
__device__ float g_bperm[GDIM];   // permuted bias (b_ih + b_hh)

__device__ __forceinline__ uint32_t f2h2(float lo, float hi) {
    __half2 p = __floats2half2_rn(lo, hi);
    return *(uint32_t*)&p;
}

#define MMA_F16(d, a, b0, b1)                                               \
    asm volatile("mma.sync.aligned.m16n8k16.row.col.f32.f16.f16.f32 "      \
                 "{%0,%1,%2,%3}, {%4,%5,%6,%7}, {%8,%9}, {%0,%1,%2,%3};"    \
                 : "+f"((d)[0]), "+f"((d)[1]), "+f"((d)[2]), "+f"((d)[3])   \
                 : "r"((a)[0]), "r"((a)[1]), "r"((a)[2]), "r"((a)[3]),      \
                   "r"(b0), "r"(b1))

// =================== prep: permute + fp16 + fragment-pack ===================
__global__ void prep_kernel(const float* __restrict__ wih,
                            const float* __restrict__ whh,
                            const float* __restrict__ bih,
                            const float* __restrict__ bhh) {
    int i = blockIdx.x * blockDim.x + threadIdx.x;   // 0..65535
    if (i >= 8*32*8*32) return;
    int lane = i & 31;
    int j    = (i >> 5) & 7;
    int kc   = (i >> 8) & 31;
    int w    = (i >> 13) & 7;
    int grp  = lane >> 2;
    int tg   = lane & 3;

    const float* W = (kc < 16) ? wih : whh;
    int kbase = (kc & 15)*16;

    uint4 v;
    #pragma unroll
    for (int h = 0; h < 2; ++h) {
        int nf = 2*j + h;
        int colperm = w*128 + nf*8 + grp;
        int unit = colperm >> 2, gate = colperm & 3;
        const float* wr = W + (gate*256 + unit)*256 + kbase;
        // b0: k rows 2tg, 2tg+1 ; b1: k rows 2tg+8, 2tg+9
        uint32_t b0 = f2h2(wr[2*tg], wr[2*tg + 1]);
        uint32_t b1 = f2h2(wr[2*tg + 8], wr[2*tg + 9]);
        if (h == 0) { v.x = b0; v.y = b1; } else { v.z = b0; v.w = b1; }
    }
    g_wpk4[i] = v;

    if (i < GDIM) {
        int u2 = i >> 2, g2 = i & 3;
        g_bperm[i] = bih[g2*256 + u2] + bhh[g2*256 + u2];
    }
}

__device__ __forceinline__ float sigmoidf_(float x) {
    return 1.0f / (1.0f + __expf(-x));
}

// =================== fused LSTM kernel (fp16 MMA, fp32 accum) ===================
__global__ __launch_bounds__(NTHREADS, 1)
void lstm_fused_kernel(const float* __restrict__ x, float* __restrict__ out) {
    extern __shared__ uint32_t sm[];           // half2 words
    uint32_t* Xs = sm;                          // [32][XSW]
    uint32_t* Hb = sm + XS_WORDS;               // 2 x [32][XSW]

    const int tid  = threadIdx.x;
    const int lane = tid & 31;
    const int w    = tid >> 5;                  // 0..7, owns gate cols w*128..+127
    const int grp  = lane >> 2;
    const int tg   = lane & 3;
    const int tgl  = tg & 1;
    const int tgh  = tg >> 1;
    const long rowbase = (long)blockIdx.x * ROWS;

    // zero h buffer 0
    for (int i = tid; i < XS_WORDS; i += NTHREADS) Hb[i] = 0u;
    __syncthreads();

    // c-state in registers
    float cst[2][16];
    #pragma unroll
    for (int a = 0; a < 2; ++a)
        #pragma unroll
        for (int b = 0; b < 16; ++b) cst[a][b] = 0.0f;

    const float* xbase = x + rowbase * (SEQ*EDIM);

    for (int s = 0; s < SEQ; ++s) {
        // ---- stage x_s tile [32][256] as fp16 half2 ----
        {
            const long srow = (long)s * EDIM;
            #pragma unroll
            for (int it = 0; it < 8; ++it) {
                int fi = tid + it * NTHREADS;    // 0..2047 float4 index
                int r  = fi >> 6;                // 64 float4 per row
                int cq = fi & 63;
                const float4 v = *((const float4*)(xbase + (long)r*(SEQ*EDIM) + srow) + cq);
                Xs[r*XSW + cq*2]     = f2h2(v.x, v.y);
                Xs[r*XSW + cq*2 + 1] = f2h2(v.z, v.w);
            }
        }
        __syncthreads();

        const uint32_t* Hcur = Hb + (s & 1) * XS_WORDS;
        __half*         Hnxt = (__half*)(Hb + ((s + 1) & 1) * XS_WORDS);
        const bool doH = (s > 0);

        // accumulators, bias-initialized
        float d[2][16][4];
        #pragma unroll
        for (int nf = 0; nf < 16; ++nf) {
            int col = w*128 + nf*8 + 2*tg;
            float b0v = g_bperm[col], b1v = g_bperm[col + 1];
            d[0][nf][0] = b0v; d[0][nf][1] = b1v; d[0][nf][2] = b0v; d[0][nf][3] = b1v;
            d[1][nf][0] = b0v; d[1][nf][1] = b1v; d[1][nf][2] = b0v; d[1][nf][3] = b1v;
        }

        // ---- X part: kc 0..15 (K=256) ----
        {
            #pragma unroll 4
            for (int kc = 0; kc < 16; ++kc) {
                const int kw = kc*8;
                uint32_t a[2][4];
                #pragma unroll
                for (int mh = 0; mh < 2; ++mh) {
                    int r0 = mh*16 + grp;
                    a[mh][0] = Xs[r0*XSW + kw + tg];
                    a[mh][1] = Xs[(r0+8)*XSW + kw + tg];
                    a[mh][2] = Xs[r0*XSW + kw + 4 + tg];
                    a[mh][3] = Xs[(r0+8)*XSW + kw + 4 + tg];
                }
                const uint4* bp = g_wpk4 + ((size_t)(w*32 + kc)*8)*32 + lane;
                #pragma unroll
                for (int j = 0; j < 8; ++j) {
                    uint4 b = bp[j*32];
                    MMA_F16(d[0][2*j],   a[0], b.x, b.y);
                    MMA_F16(d[1][2*j],   a[1], b.x, b.y);
                    MMA_F16(d[0][2*j+1], a[0], b.z, b.w);
                    MMA_F16(d[1][2*j+1], a[1], b.z, b.w);
                }
            }
        }
        // ---- H part: kc 16..31 (K=256) ----
        if (doH) {
            #pragma unroll 4
            for (int kc = 0; kc < 16; ++kc) {
                const int kw = kc*8;
                uint32_t a[2][4];
                #pragma unroll
                for (int mh = 0; mh < 2; ++mh) {
                    int r0 = mh*16 + grp;
                    a[mh][0] = Hcur[r0*XSW + kw + tg];
                    a[mh][1] = Hcur[(r0+8)*XSW + kw + tg];
                    a[mh][2] = Hcur[r0*XSW + kw + 4 + tg];
                    a[mh][3] = Hcur[(r0+8)*XSW + kw + 4 + tg];
                }
                const uint4* bp = g_wpk4 + ((size_t)(w*32 + 16 + kc)*8)*32 + lane;
                #pragma unroll
                for (int j = 0; j < 8; ++j) {
                    uint4 b = bp[j*32];
                    MMA_F16(d[0][2*j],   a[0], b.x, b.y);
                    MMA_F16(d[1][2*j],   a[1], b.x, b.y);
                    MMA_F16(d[0][2*j+1], a[0], b.z, b.w);
                    MMA_F16(d[1][2*j+1], a[1], b.z, b.w);
                }
            }
        }

        // ---- activation in registers ----
        #pragma unroll
        for (int mh = 0; mh < 2; ++mh) {
            #pragma unroll
            for (int nf = 0; nf < 16; ++nf) {
                float c0 = d[mh][nf][0], c1 = d[mh][nf][1];
                float c2 = d[mh][nf][2], c3 = d[mh][nf][3];
                float x0 = __shfl_xor_sync(0xffffffffu, tgl ? c0 : c2, 1);
                float x1 = __shfl_xor_sync(0xffffffffu, tgl ? c1 : c3, 1);
                float gi = tgl ? x0 : c0;
                float gf = tgl ? x1 : c1;
                float gg = tgl ? c2 : x0;
                float go = tgl ? c3 : x1;
                int row = grp + 8*tgl + 16*mh;
                int u   = w*32 + 2*nf + tgh;        // global unit 0..255
                float cv = sigmoidf_(gf) * cst[mh][nf]
                         + sigmoidf_(gi) * tanhf(gg);
                cst[mh][nf] = cv;
                float h = sigmoidf_(go) * tanhf(cv);
                Hnxt[row*(2*XSW) + u] = __float2half_rn(h);
                if (s == SEQ - 1) out[(rowbase + row)*HDIM + u] = h;
            }
        }
        __syncthreads();
    }
}

extern "C" void kernel_launch(void* const* d_in, const int* in_sizes, int n_in,
                              void* d_out, int out_size) {
    const float* x   = (const float*)d_in[0];
    const float* wih = (const float*)d_in[1];
    const float* whh = (const float*)d_in[2];
    const float* bih = (const float*)d_in[3];
    const float* bhh = (const float*)d_in[4];
    float* out = (float*)d_out;

    cudaFuncSetAttribute(lstm_fused_kernel,
                         cudaFuncAttributeMaxDynamicSharedMemorySize, SMEM_BYTES);

    prep_kernel<<<(8*32*8*32 + 255)/256, 256>>>(wih, whh, bih, bhh);
    lstm_fused_kernel<<<NCTAS, NTHREADS, SMEM_BYTES>>>(x, out);
}

// round 11
// speedup vs baseline: 2.0487x; 1.0582x over previous
#include <cuda_runtime.h>
#include <cuda_fp16.h>
#include <cstdint>

#define SEQ 32
#define EDIM 256
#define HDIM 256
#define GDIM 1024
#define ROWS 32
#define NCTAS 128
#define NTHREADS 512
#define NWARPS 16

#define XSW 132   // half2 words per row (264 halves): conflict-free
#define XS_WORDS (ROWS*XSW)
#define SMEM_BYTES ((XS_WORDS + 2*XS_WORDS)*4)   // Xs + 2 H buffers = 50,688 B

// fp16 B-fragment packed weights, uint4 pairs (nf 2j, 2j+1):
// index = ((w*32 + kc)*4 + j)*32 + lane ; w = warp 0..15 (64-col slice),
// kc 0..15 = X part (W_ih), 16..31 = H part (W_hh)
__device__ __align__(16) uint4 g_wpk4[NWARPS*32*4*32];
__device__ float g_bperm[GDIM];   // permuted bias (b_ih + b_hh)

__device__ __forceinline__ uint32_t f2h2(float lo, float hi) {
    __half2 p = __floats2half2_rn(lo, hi);
    return *(uint32_t*)&p;
}

#define MMA_F16(d, a, b0, b1)                                               \
    asm volatile("mma.sync.aligned.m16n8k16.row.col.f32.f16.f16.f32 "      \
                 "{%0,%1,%2,%3}, {%4,%5,%6,%7}, {%8,%9}, {%0,%1,%2,%3};"    \
                 : "+f"((d)[0]), "+f"((d)[1]), "+f"((d)[2]), "+f"((d)[3])   \
                 : "r"((a)[0]), "r"((a)[1]), "r"((a)[2]), "r"((a)[3]),      \
                   "r"(b0), "r"(b1))

// =================== prep: permute + fp16 + fragment-pack ===================
__global__ void prep_kernel(const float* __restrict__ wih,
                            const float* __restrict__ whh,
                            const float* __restrict__ bih,
                            const float* __restrict__ bhh) {
    int i = blockIdx.x * blockDim.x + threadIdx.x;   // 0..65535
    if (i >= NWARPS*32*4*32) return;
    int lane = i & 31;
    int j    = (i >> 5) & 3;
    int kc   = (i >> 7) & 31;
    int w    = (i >> 12) & 15;
    int grp  = lane >> 2;
    int tg   = lane & 3;

    const float* W = (kc < 16) ? wih : whh;
    int kbase = (kc & 15)*16;

    uint4 v;
    #pragma unroll
    for (int h = 0; h < 2; ++h) {
        int nf = 2*j + h;
        int colperm = w*64 + nf*8 + grp;
        int unit = colperm >> 2, gate = colperm & 3;
        const float* wr = W + (gate*256 + unit)*256 + kbase;
        uint32_t b0 = f2h2(wr[2*tg], wr[2*tg + 1]);
        uint32_t b1 = f2h2(wr[2*tg + 8], wr[2*tg + 9]);
        if (h == 0) { v.x = b0; v.y = b1; } else { v.z = b0; v.w = b1; }
    }
    g_wpk4[i] = v;

    if (i < GDIM) {
        int u2 = i >> 2, g2 = i & 3;
        g_bperm[i] = bih[g2*256 + u2] + bhh[g2*256 + u2];
    }
}

__device__ __forceinline__ float sigmoidf_(float x) {
    return 1.0f / (1.0f + __expf(-x));
}

// =================== fused LSTM kernel (fp16 MMA, fp32 accum, 16 warps) ===================
__global__ __launch_bounds__(NTHREADS, 1)
void lstm_fused_kernel(const float* __restrict__ x, float* __restrict__ out) {
    extern __shared__ uint32_t sm[];           // half2 words
    uint32_t* Xs = sm;                          // [32][XSW]
    uint32_t* Hb = sm + XS_WORDS;               // 2 x [32][XSW]

    const int tid  = threadIdx.x;
    const int lane = tid & 31;
    const int w    = tid >> 5;                  // 0..15, owns gate cols w*64..+63
    const int grp  = lane >> 2;
    const int tg   = lane & 3;
    const int tgl  = tg & 1;
    const int tgh  = tg >> 1;
    const long rowbase = (long)blockIdx.x * ROWS;

    // zero h buffer 0
    for (int i = tid; i < XS_WORDS; i += NTHREADS) Hb[i] = 0u;
    __syncthreads();

    // c-state in registers
    float cst[2][8];
    #pragma unroll
    for (int a = 0; a < 2; ++a)
        #pragma unroll
        for (int b = 0; b < 8; ++b) cst[a][b] = 0.0f;

    const float* xbase = x + rowbase * (SEQ*EDIM);

    for (int s = 0; s < SEQ; ++s) {
        // ---- stage x_s tile [32][256] as fp16 half2 ----
        {
            const long srow = (long)s * EDIM;
            #pragma unroll
            for (int it = 0; it < 4; ++it) {
                int fi = tid + it * NTHREADS;    // 0..2047 float4 index
                int r  = fi >> 6;
                int cq = fi & 63;
                const float4 v = *((const float4*)(xbase + (long)r*(SEQ*EDIM) + srow) + cq);
                Xs[r*XSW + cq*2]     = f2h2(v.x, v.y);
                Xs[r*XSW + cq*2 + 1] = f2h2(v.z, v.w);
            }
        }
        __syncthreads();

        const uint32_t* Hcur = Hb + (s & 1) * XS_WORDS;
        __half*         Hnxt = (__half*)(Hb + ((s + 1) & 1) * XS_WORDS);
        const bool doH = (s > 0);

        // accumulators, bias-initialized
        float d[2][8][4];
        #pragma unroll
        for (int nf = 0; nf < 8; ++nf) {
            int col = w*64 + nf*8 + 2*tg;
            float b0v = g_bperm[col], b1v = g_bperm[col + 1];
            d[0][nf][0] = b0v; d[0][nf][1] = b1v; d[0][nf][2] = b0v; d[0][nf][3] = b1v;
            d[1][nf][0] = b0v; d[1][nf][1] = b1v; d[1][nf][2] = b0v; d[1][nf][3] = b1v;
        }

        // ---- X part: kc 0..15 (K=256) ----
        {
            #pragma unroll 4
            for (int kc = 0; kc < 16; ++kc) {
                const int kw = kc*8;
                uint32_t a[2][4];
                #pragma unroll
                for (int mh = 0; mh < 2; ++mh) {
                    int r0 = mh*16 + grp;
                    a[mh][0] = Xs[r0*XSW + kw + tg];
                    a[mh][1] = Xs[(r0+8)*XSW + kw + tg];
                    a[mh][2] = Xs[r0*XSW + kw + 4 + tg];
                    a[mh][3] = Xs[(r0+8)*XSW + kw + 4 + tg];
                }
                const uint4* bp = g_wpk4 + ((size_t)(w*32 + kc)*4)*32 + lane;
                #pragma unroll
                for (int j = 0; j < 4; ++j) {
                    uint4 b = bp[j*32];
                    MMA_F16(d[0][2*j],   a[0], b.x, b.y);
                    MMA_F16(d[1][2*j],   a[1], b.x, b.y);
                    MMA_F16(d[0][2*j+1], a[0], b.z, b.w);
                    MMA_F16(d[1][2*j+1], a[1], b.z, b.w);
                }
            }
        }
        // ---- H part: kc 16..31 (K=256) ----
        if (doH) {
            #pragma unroll 4
            for (int kc = 0; kc < 16; ++kc) {
                const int kw = kc*8;
                uint32_t a[2][4];
                #pragma unroll
                for (int mh = 0; mh < 2; ++mh) {
                    int r0 = mh*16 + grp;
                    a[mh][0] = Hcur[r0*XSW + kw + tg];
                    a[mh][1] = Hcur[(r0+8)*XSW + kw + tg];
                    a[mh][2] = Hcur[r0*XSW + kw + 4 + tg];
                    a[mh][3] = Hcur[(r0+8)*XSW + kw + 4 + tg];
                }
                const uint4* bp = g_wpk4 + ((size_t)(w*32 + 16 + kc)*4)*32 + lane;
                #pragma unroll
                for (int j = 0; j < 4; ++j) {
                    uint4 b = bp[j*32];
                    MMA_F16(d[0][2*j],   a[0], b.x, b.y);
                    MMA_F16(d[1][2*j],   a[1], b.x, b.y);
                    MMA_F16(d[0][2*j+1], a[0], b.z, b.w);
                    MMA_F16(d[1][2*j+1], a[1], b.z, b.w);
                }
            }
        }

        // ---- activation in registers ----
        #pragma unroll
        for (int mh = 0; mh < 2; ++mh) {
            #pragma unroll
            for (int nf = 0; nf < 8; ++nf) {
                float c0 = d[mh][nf][0], c1 = d[mh][nf][1];
                float c2 = d[mh][nf][2], c3 = d[mh][nf][3];
                float x0 = __shfl_xor_sync(0xffffffffu, tgl ? c0 : c2, 1);
                float x1 = __shfl_xor_sync(0xffffffffu, tgl ? c1 : c3, 1);
                float gi = tgl ? x0 : c0;
                float gf = tgl ? x1 : c1;
                float gg = tgl ? c2 : x0;
                float go = tgl ? c3 : x1;
                int row = grp + 8*tgl + 16*mh;
                int u   = w*16 + 2*nf + tgh;        // global unit 0..255
                float cv = sigmoidf_(gf) * cst[mh][nf]
                         + sigmoidf_(gi) * tanhf(gg);
                cst[mh][nf] = cv;
                float h = sigmoidf_(go) * tanhf(cv);
                Hnxt[row*(2*XSW) + u] = __float2half_rn(h);
                if (s == SEQ - 1) out[(rowbase + row)*HDIM + u] = h;
            }
        }
        __syncthreads();
    }
}

extern "C" void kernel_launch(void* const* d_in, const int* in_sizes, int n_in,
                              void* d_out, int out_size) {
    const float* x   = (const float*)d_in[0];
    const float* wih = (const float*)d_in[1];
    const float* whh = (const float*)d_in[2];
    const float* bih = (const float*)d_in[3];
    const float* bhh = (const float*)d_in[4];
    float* out = (float*)d_out;

    cudaFuncSetAttribute(lstm_fused_kernel,
                         cudaFuncAttributeMaxDynamicSharedMemorySize, SMEM_BYTES);

    prep_kernel<<<(NWARPS*32*4*32 + 255)/256, 256>>>(wih, whh, bih, bhh);
    lstm_fused_kernel<<<NCTAS, NTHREADS, SMEM_BYTES>>>(x, out);
}

// round 12
// speedup vs baseline: 2.8394x; 1.3860x over previous
#include <cuda_runtime.h>
#include <cuda_fp16.h>
#include <cstdint>

#define SEQ 32
#define EDIM 256
#define HDIM 256
#define GDIM 1024
#define ROWS 32
#define NCTAS 128
#define NTHREADS 512
#define NWARPS 16

#define XSW 132   // half2 words per row (264 halves): conflict-free
#define XS_WORDS (ROWS*XSW)
#define SMEM_BYTES ((XS_WORDS + 2*XS_WORDS)*4)   // Xs + 2 H buffers = 50,688 B

// fp16 B-fragment packed weights, uint4 pairs (nf 2j, 2j+1):
// index = ((w*32 + kc)*4 + j)*32 + lane ; w = warp 0..15 (64-col slice),
// kc 0..15 = X part (W_ih), 16..31 = H part (W_hh)
__device__ __align__(16) uint4 g_wpk4[NWARPS*32*4*32];
__device__ float g_bperm[GDIM];   // permuted bias (b_ih + b_hh)

__device__ __forceinline__ uint32_t f2h2(float lo, float hi) {
    __half2 p = __floats2half2_rn(lo, hi);
    return *(uint32_t*)&p;
}
__device__ __forceinline__ float tanh_fast(float x) {
    float r; asm("tanh.approx.f32 %0, %1;" : "=f"(r) : "f"(x)); return r;
}
__device__ __forceinline__ float sigmoid_fast(float x) {
    return fmaf(0.5f, tanh_fast(0.5f * x), 0.5f);
}

#define MMA_F16(d, a, b0, b1)                                               \
    asm volatile("mma.sync.aligned.m16n8k16.row.col.f32.f16.f16.f32 "      \
                 "{%0,%1,%2,%3}, {%4,%5,%6,%7}, {%8,%9}, {%0,%1,%2,%3};"    \
                 : "+f"((d)[0]), "+f"((d)[1]), "+f"((d)[2]), "+f"((d)[3])   \
                 : "r"((a)[0]), "r"((a)[1]), "r"((a)[2]), "r"((a)[3]),      \
                   "r"(b0), "r"(b1))

// =================== prep: permute + fp16 + fragment-pack ===================
__global__ void prep_kernel(const float* __restrict__ wih,
                            const float* __restrict__ whh,
                            const float* __restrict__ bih,
                            const float* __restrict__ bhh) {
    int i = blockIdx.x * blockDim.x + threadIdx.x;   // 0..65535
    if (i >= NWARPS*32*4*32) return;
    int lane = i & 31;
    int j    = (i >> 5) & 3;
    int kc   = (i >> 7) & 31;
    int w    = (i >> 12) & 15;
    int grp  = lane >> 2;
    int tg   = lane & 3;

    const float* W = (kc < 16) ? wih : whh;
    int kbase = (kc & 15)*16;

    uint4 v;
    #pragma unroll
    for (int h = 0; h < 2; ++h) {
        int nf = 2*j + h;
        int colperm = w*64 + nf*8 + grp;
        int unit = colperm >> 2, gate = colperm & 3;
        const float* wr = W + (gate*256 + unit)*256 + kbase;
        uint32_t b0 = f2h2(wr[2*tg], wr[2*tg + 1]);
        uint32_t b1 = f2h2(wr[2*tg + 8], wr[2*tg + 9]);
        if (h == 0) { v.x = b0; v.y = b1; } else { v.z = b0; v.w = b1; }
    }
    g_wpk4[i] = v;

    if (i < GDIM) {
        int u2 = i >> 2, g2 = i & 3;
        g_bperm[i] = bih[g2*256 + u2] + bhh[g2*256 + u2];
    }
}

// =================== fused LSTM kernel (fp16 MMA, fp32 accum, pipelined) ===================
__global__ __launch_bounds__(NTHREADS, 1)
void lstm_fused_kernel(const float* __restrict__ x, float* __restrict__ out) {
    extern __shared__ uint32_t sm[];           // half2 words
    uint32_t* Xs = sm;                          // [32][XSW]
    uint32_t* Hb = sm + XS_WORDS;               // 2 x [32][XSW]

    const int tid  = threadIdx.x;
    const int lane = tid & 31;
    const int w    = tid >> 5;                  // 0..15, owns gate cols w*64..+63
    const int grp  = lane >> 2;
    const int tg   = lane & 3;
    const int tgl  = tg & 1;
    const int tgh  = tg >> 1;
    const long rowbase = (long)blockIdx.x * ROWS;

    for (int i = tid; i < XS_WORDS; i += NTHREADS) Hb[i] = 0u;
    __syncthreads();

    float cst[2][8];
    #pragma unroll
    for (int a = 0; a < 2; ++a)
        #pragma unroll
        for (int b = 0; b < 8; ++b) cst[a][b] = 0.0f;

    const float* xbase = x + rowbase * (SEQ*EDIM);
    const uint4* wbase = g_wpk4 + ((size_t)w*32*4)*32 + lane;

    for (int s = 0; s < SEQ; ++s) {
        // ---- stage x_s tile [32][256] as fp16 half2 ----
        {
            const long srow = (long)s * EDIM;
            #pragma unroll
            for (int it = 0; it < 4; ++it) {
                int fi = tid + it * NTHREADS;
                int r  = fi >> 6;
                int cq = fi & 63;
                const float4 v = *((const float4*)(xbase + (long)r*(SEQ*EDIM) + srow) + cq);
                Xs[r*XSW + cq*2]     = f2h2(v.x, v.y);
                Xs[r*XSW + cq*2 + 1] = f2h2(v.z, v.w);
            }
        }
        __syncthreads();

        const uint32_t* Hcur = Hb + (s & 1) * XS_WORDS;
        __half*         Hnxt = (__half*)(Hb + ((s + 1) & 1) * XS_WORDS);
        const int nkc = (s == 0) ? 16 : 32;     // s=0: h=0, skip H part

        // accumulators, bias-initialized
        float d[2][8][4];
        #pragma unroll
        for (int nf = 0; nf < 8; ++nf) {
            int col = w*64 + nf*8 + 2*tg;
            float b0v = g_bperm[col], b1v = g_bperm[col + 1];
            d[0][nf][0] = b0v; d[0][nf][1] = b1v; d[0][nf][2] = b0v; d[0][nf][3] = b1v;
            d[1][nf][0] = b0v; d[1][nf][1] = b1v; d[1][nf][2] = b0v; d[1][nf][3] = b1v;
        }

        // ---- merged X+H mainloop, 2-slot software pipeline ----
        uint4   wb[2][4];
        uint32_t ab[2][8];
        // prologue: fetch kc=0
        {
            const uint4* bp = wbase;
            #pragma unroll
            for (int j = 0; j < 4; ++j) wb[0][j] = bp[j*32];
            const int kw = 0;
            #pragma unroll
            for (int mh = 0; mh < 2; ++mh) {
                int r0 = mh*16 + grp;
                ab[0][mh*4+0] = Xs[r0*XSW + kw + tg];
                ab[0][mh*4+1] = Xs[(r0+8)*XSW + kw + tg];
                ab[0][mh*4+2] = Xs[r0*XSW + kw + 4 + tg];
                ab[0][mh*4+3] = Xs[(r0+8)*XSW + kw + 4 + tg];
            }
        }

        #pragma unroll 2
        for (int kc = 0; kc < nkc; ++kc) {
            const int cur = kc & 1, nxt = cur ^ 1;
            // prefetch kc+1 (weights via LDG, a-frags via LDS)
            if (kc + 1 < nkc) {
                const uint4* bp = wbase + (size_t)(kc + 1)*4*32;
                #pragma unroll
                for (int j = 0; j < 4; ++j) wb[nxt][j] = bp[j*32];
                const uint32_t* A = (kc + 1 < 16) ? Xs : Hcur;
                const int kw = ((kc + 1) & 15)*8;
                #pragma unroll
                for (int mh = 0; mh < 2; ++mh) {
                    int r0 = mh*16 + grp;
                    ab[nxt][mh*4+0] = A[r0*XSW + kw + tg];
                    ab[nxt][mh*4+1] = A[(r0+8)*XSW + kw + tg];
                    ab[nxt][mh*4+2] = A[r0*XSW + kw + 4 + tg];
                    ab[nxt][mh*4+3] = A[(r0+8)*XSW + kw + 4 + tg];
                }
            }
            // compute kc
            #pragma unroll
            for (int j = 0; j < 4; ++j) {
                uint4 b = wb[cur][j];
                MMA_F16(d[0][2*j],   &ab[cur][0], b.x, b.y);
                MMA_F16(d[1][2*j],   &ab[cur][4], b.x, b.y);
                MMA_F16(d[0][2*j+1], &ab[cur][0], b.z, b.w);
                MMA_F16(d[1][2*j+1], &ab[cur][4], b.z, b.w);
            }
        }

        // ---- activation in registers (tanh.approx) ----
        #pragma unroll
        for (int mh = 0; mh < 2; ++mh) {
            #pragma unroll
            for (int nf = 0; nf < 8; ++nf) {
                float c0 = d[mh][nf][0], c1 = d[mh][nf][1];
                float c2 = d[mh][nf][2], c3 = d[mh][nf][3];
                float x0 = __shfl_xor_sync(0xffffffffu, tgl ? c0 : c2, 1);
                float x1 = __shfl_xor_sync(0xffffffffu, tgl ? c1 : c3, 1);
                float gi = tgl ? x0 : c0;
                float gf = tgl ? x1 : c1;
                float gg = tgl ? c2 : x0;
                float go = tgl ? c3 : x1;
                int row = grp + 8*tgl + 16*mh;
                int u   = w*16 + 2*nf + tgh;        // global unit 0..255
                float cv = sigmoid_fast(gf) * cst[mh][nf]
                         + sigmoid_fast(gi) * tanh_fast(gg);
                cst[mh][nf] = cv;
                float h = sigmoid_fast(go) * tanh_fast(cv);
                Hnxt[row*(2*XSW) + u] = __float2half_rn(h);
                if (s == SEQ - 1) out[(rowbase + row)*HDIM + u] = h;
            }
        }
        __syncthreads();
    }
}

extern "C" void kernel_launch(void* const* d_in, const int* in_sizes, int n_in,
                              void* d_out, int out_size) {
    const float* x   = (const float*)d_in[0];
    const float* wih = (const float*)d_in[1];
    const float* whh = (const float*)d_in[2];
    const float* bih = (const float*)d_in[3];
    const float* bhh = (const float*)d_in[4];
    float* out = (float*)d_out;

    cudaFuncSetAttribute(lstm_fused_kernel,
                         cudaFuncAttributeMaxDynamicSharedMemorySize, SMEM_BYTES);

    prep_kernel<<<(NWARPS*32*4*32 + 255)/256, 256>>>(wih, whh, bih, bhh);
    lstm_fused_kernel<<<NCTAS, NTHREADS, SMEM_BYTES>>>(x, out);
}